// round 14
// baseline (speedup 1.0000x reference)
#include <cuda_runtime.h>
#include <cuda_bf16.h>
#include <cstdint>

// Problem constants
#define BIMG   128
#define NOBJ_  36
#define NNODES (BIMG * NOBJ_)   // 4608
#define QD_    2400
#define VD_    2048
#define KPAD_Q 2432             // 2400 padded to multiple of 32

typedef __nv_bfloat16 bf16;

// ---------------- scratch (device globals; no allocation allowed) -------------
__device__ float g_q  [BIMG   * 2048];          // q fp32 (split-K accumulated)
__device__ float g_h  [NNODES * 2560];          // h1/h2/h3 (fp32, attention input)
__device__ float g_g1 [NNODES * 1024];          // g1 fp32 (residual)
__device__ float g_a3 [NNODES * 2560];          // layer-3 per-head agg

__device__ bf16 g_qe_h [BIMG * KPAD_Q],  g_qe_l [BIMG * KPAD_Q];
__device__ bf16 g_obj_h[NNODES * 2048],  g_obj_l[NNODES * 2048];
__device__ bf16 g_x_h  [NNODES * 2048],  g_x_l  [NNODES * 2048];
__device__ bf16 g_g1_h [NNODES * 1024],  g_g1_l [NNODES * 1024];
__device__ bf16 g_g2_h [NNODES * 1024],  g_g2_l [NNODES * 1024];

// weights transposed to [N, Kpad], split into bf16 hi/lo
__device__ bf16 g_Wq_hi[2048 * KPAD_Q], g_Wq_lo[2048 * KPAD_Q];
__device__ bf16 g_Wv_hi[2048 * 2048],   g_Wv_lo[2048 * 2048];
__device__ bf16 g_W1_hi[1024 * 2048],   g_W1_lo[1024 * 2048];
__device__ bf16 g_W2_hi[1024 * 1024],   g_W2_lo[1024 * 1024];
__device__ bf16 g_W3_hi[2560 * 1024],   g_W3_lo[2560 * 1024];

// ---------------- small helpers -------------------------------------------------
__device__ __forceinline__ uint32_t smem_u32(const void* p) {
    uint32_t a;
    asm("{ .reg .u64 t; cvta.to.shared.u64 t, %1; cvt.u32.u64 %0, t; }" : "=r"(a) : "l"(p));
    return a;
}
__device__ __forceinline__ void cp_async16(uint32_t dst, const void* src) {
    asm volatile("cp.async.cg.shared.global [%0], [%1], 16;" :: "r"(dst), "l"(src));
}
__device__ __forceinline__ void cp_commit() { asm volatile("cp.async.commit_group;"); }
__device__ __forceinline__ void ldm_x4(uint32_t* r, uint32_t addr) {
    asm volatile("ldmatrix.sync.aligned.m8n8.x4.shared.b16 {%0,%1,%2,%3}, [%4];"
                 : "=r"(r[0]), "=r"(r[1]), "=r"(r[2]), "=r"(r[3]) : "r"(addr));
}
__device__ __forceinline__ void mma16816(float* c, const uint32_t* a, uint32_t b0, uint32_t b1) {
    asm volatile("mma.sync.aligned.m16n8k16.row.col.f32.bf16.bf16.f32 "
                 "{%0,%1,%2,%3}, {%4,%5,%6,%7}, {%8,%9}, {%0,%1,%2,%3};"
                 : "+f"(c[0]), "+f"(c[1]), "+f"(c[2]), "+f"(c[3])
                 : "r"(a[0]), "r"(a[1]), "r"(a[2]), "r"(a[3]), "r"(b0), "r"(b1));
}
__device__ __forceinline__ void split_bf16(float v, bf16& h, bf16& l) {
    h = __float2bfloat16(v);
    l = __float2bfloat16(v - __bfloat162float(h));
}

// ---------------- weight prep: W[K,N] fp32 -> Wt_hi/lo [N,Kpad] bf16 ------------
__global__ __launch_bounds__(256) void prep_w(
    int K, int N, int Kpad, const float* __restrict__ W,
    bf16* __restrict__ hi, bf16* __restrict__ lo)
{
    __shared__ float t[32][33];
    const int n0 = blockIdx.x * 32, k0 = blockIdx.y * 32;
    const int tx = threadIdx.x, ty = threadIdx.y;   // 32 x 8
#pragma unroll
    for (int i = 0; i < 4; i++) {
        const int k = k0 + ty + i * 8;
        t[ty + i * 8][tx] = (k < K) ? W[(size_t)k * N + n0 + tx] : 0.f;
    }
    __syncthreads();
#pragma unroll
    for (int i = 0; i < 4; i++) {
        const int n = n0 + ty + i * 8;
        const float v = t[tx][ty + i * 8];
        bf16 h, l; split_bf16(v, h, l);
        hi[(size_t)n * Kpad + k0 + tx] = h;
        lo[(size_t)n * Kpad + k0 + tx] = l;
    }
}

// ---------------- activation conv: fp32 [M,K] -> bf16 hi/lo [M,Kpad] ------------
__global__ __launch_bounds__(256) void conv_pair(
    const float* __restrict__ src, bf16* __restrict__ hi, bf16* __restrict__ lo,
    int K, int Kpad)
{
    const int c4 = blockIdx.x * blockDim.x + threadIdx.x;
    if (c4 * 4 >= Kpad) return;
    const int r = blockIdx.y;
    float4 v;
    if (c4 * 4 + 4 <= K) v = *(const float4*)&src[(size_t)r * K + c4 * 4];
    else                 v = make_float4(0.f, 0.f, 0.f, 0.f);
    bf16 h0, l0, h1, l1, h2, l2, h3, l3;
    split_bf16(v.x, h0, l0); split_bf16(v.y, h1, l1);
    split_bf16(v.z, h2, l2); split_bf16(v.w, h3, l3);
    const size_t o = (size_t)r * Kpad + c4 * 4;
    *(__nv_bfloat162*)&hi[o]     = __nv_bfloat162(h0, h1);
    *(__nv_bfloat162*)&hi[o + 2] = __nv_bfloat162(h2, h3);
    *(__nv_bfloat162*)&lo[o]     = __nv_bfloat162(l0, l1);
    *(__nv_bfloat162*)&lo[o + 2] = __nv_bfloat162(l2, l3);
}

// ---------------- zero-fill -----------------------------------------------------
__global__ __launch_bounds__(256) void zero_kernel(float* __restrict__ p, int n)
{
    const int i = blockIdx.x * blockDim.x + threadIdx.x;
    if (i < n) p[i] = 0.f;
}

// ---------------- HMMA bf16x3 GEMM (R9 shape: 256 thr, 2x4 warps, 64x32) --------
// C[M,N] = A[M,K] @ Bt[N,K]^T where A,Bt are hi/lo bf16 splits.
// mode 0: C = acc (fp32)
// mode 2: (acc + bias) * (qmat[row/36] + qbias)  -> Chi/Clo bf16 pair
// mode 3: atomicAdd into C (split-K accumulation; grid.z = #chunks, nk iters each)
#define BM 128
#define BN 128
#define BK 32
#define GEMM_THREADS 256
#define KSTRIDE 40                     // padded smem row stride (bf16 elems)
#define MAT_BYTES (BM * KSTRIDE * 2)   // 10240
#define STAGE_BYTES (4 * MAT_BYTES)    // Ah, Al, Bh, Bl
#define GEMM_SMEM (2 * STAGE_BYTES)    // 81920

__global__ __launch_bounds__(GEMM_THREADS, 2) void hgemm(
    int N, int K, int nk,
    const bf16* __restrict__ Ah, const bf16* __restrict__ Al,
    const bf16* __restrict__ Bh, const bf16* __restrict__ Bl,
    float* __restrict__ C, bf16* __restrict__ Chi, bf16* __restrict__ Clo,
    const float* __restrict__ bias, const float* __restrict__ qmat,
    const float* __restrict__ qbias, int mode)
{
    extern __shared__ __align__(128) char smem[];
    const uint32_t sbase = smem_u32(smem);
    const int tid = threadIdx.x, wid = tid >> 5, lane = tid & 31;
    const int warp_m = wid >> 2, warp_n = wid & 3;       // 2 x 4 warps
    const int brow = blockIdx.y * BM, bcol = blockIdx.x * BN;
    const int k_begin = blockIdx.z * nk * BK;

    float acc[4][4][4];
#pragma unroll
    for (int m = 0; m < 4; m++)
#pragma unroll
        for (int n = 0; n < 4; n++)
#pragma unroll
            for (int e = 0; e < 4; e++) acc[m][n][e] = 0.f;

    // ---- gmem -> smem stage loader (cp.async, 16B granules) ----
    auto load_stage = [&](int buf, int k0) {
        const uint32_t s = sbase + buf * STAGE_BYTES;
#pragma unroll
        for (int it = 0; it < 2; it++) {
            const int idx = tid + it * 256;       // 0..511
            const int r = idx >> 2, c = (idx & 3) * 8;
            const uint32_t so = (uint32_t)(r * KSTRIDE + c) * 2;
            const size_t ga = (size_t)(brow + r) * K + k0 + c;
            const size_t gb = (size_t)(bcol + r) * K + k0 + c;
            cp_async16(s + so,                 Ah + ga);
            cp_async16(s + MAT_BYTES + so,     Al + ga);
            cp_async16(s + 2 * MAT_BYTES + so, Bh + gb);
            cp_async16(s + 3 * MAT_BYTES + so, Bl + gb);
        }
        cp_commit();
    };

    load_stage(0, k_begin);
    if (nk > 1) load_stage(1, k_begin + BK);
    else        cp_commit();

    // ldmatrix lane addressing (byte offsets within a matrix)
    const int a_row = lane & 15, a_k8 = (lane >> 4) * 8;
    const uint32_t aoff = (uint32_t)((warp_m * 64 + a_row) * KSTRIDE + a_k8) * 2;
    const int bmat = lane >> 3, brl = lane & 7;
    const int b_n = warp_n * 32 + (bmat >> 1) * 8 + brl;
    const int b_k = (bmat & 1) * 8;
    const uint32_t boff = (uint32_t)(b_n * KSTRIDE + b_k) * 2;

    for (int kt = 0; kt < nk; kt++) {
        asm volatile("cp.async.wait_group 1;");
        __syncthreads();

        const uint32_t s = sbase + (kt & 1) * STAGE_BYTES;
        const uint32_t sAh = s + aoff;
        const uint32_t sAl = sAh + MAT_BYTES;
        const uint32_t sBh = s + 2 * MAT_BYTES + boff;
        const uint32_t sBl = sBh + MAT_BYTES;

#pragma unroll
        for (int ks = 0; ks < 2; ks++) {
            uint32_t ah[4][4], al[4][4];
#pragma unroll
            for (int m = 0; m < 4; m++) {
                const uint32_t o = (uint32_t)(m * 16 * KSTRIDE + ks * 16) * 2;
                ldm_x4(ah[m], sAh + o);
                ldm_x4(al[m], sAl + o);
            }
#pragma unroll
            for (int np = 0; np < 2; np++) {
                uint32_t bh[4], bl[4];
                const uint32_t o = (uint32_t)(np * 16 * KSTRIDE + ks * 16) * 2;
                ldm_x4(bh, sBh + o);
                ldm_x4(bl, sBl + o);
#pragma unroll
                for (int m = 0; m < 4; m++)
#pragma unroll
                    for (int nsel = 0; nsel < 2; nsel++) {
                        float* a4 = acc[m][np * 2 + nsel];
                        mma16816(a4, ah[m], bh[nsel * 2], bh[nsel * 2 + 1]);
                        mma16816(a4, al[m], bh[nsel * 2], bh[nsel * 2 + 1]);
                        mma16816(a4, ah[m], bl[nsel * 2], bl[nsel * 2 + 1]);
                    }
            }
        }
        __syncthreads();

        const int kn = kt + 2;
        if (kn < nk) load_stage(kn & 1, k_begin + kn * BK);
        else         cp_commit();   // keep group accounting aligned
    }
    asm volatile("cp.async.wait_group 0;");

    // ---- epilogue (register -> gmem direct) ----
#pragma unroll
    for (int m = 0; m < 4; m++) {
        const int r0 = brow + warp_m * 64 + m * 16 + (lane >> 2);
#pragma unroll
        for (int n = 0; n < 4; n++) {
            const int col = bcol + warp_n * 32 + n * 8 + (lane & 3) * 2;
#pragma unroll
            for (int half = 0; half < 2; half++) {
                const int row = r0 + half * 8;
                float v0 = acc[m][n][half * 2 + 0];
                float v1 = acc[m][n][half * 2 + 1];
                if (mode == 2) {
                    const size_t qo = (size_t)(row / NOBJ_) * N + col;
                    v0 = (v0 + bias[col])     * (qmat[qo]     + qbias[col]);
                    v1 = (v1 + bias[col + 1]) * (qmat[qo + 1] + qbias[col + 1]);
                    bf16 h0, l0, h1, l1;
                    split_bf16(v0, h0, l0); split_bf16(v1, h1, l1);
                    *(__nv_bfloat162*)&Chi[(size_t)row * N + col] = __nv_bfloat162(h0, h1);
                    *(__nv_bfloat162*)&Clo[(size_t)row * N + col] = __nv_bfloat162(l0, l1);
                } else if (mode == 3) {
                    atomicAdd(&C[(size_t)row * N + col],     v0);
                    atomicAdd(&C[(size_t)row * N + col + 1], v1);
                } else {
                    *(float2*)&C[(size_t)row * N + col] = make_float2(v0, v1);
                }
            }
        }
    }
}

// ---------------- per-(image, head) dense GAT attention -------------------------
// MODE 0: g = relu(agg+bias); out fp32 + hi/lo pair
// MODE 1: g = relu(agg+bias) + res; out hi/lo pair only
// MODE 2: out = agg (fp32 only)
#define RAWP 37
template <int HEADS, int C, int MODE>
__global__ __launch_bounds__(256) void gat_attn(
    const float* __restrict__ h,
    const float* __restrict__ a_src, const float* __restrict__ a_dst,
    const float* __restrict__ bias,  const float* __restrict__ res,
    float* __restrict__ out, bf16* __restrict__ outH, bf16* __restrict__ outL)
{
    extern __shared__ float sm[];
    float* hs  = sm;                       // 36*C
    float* raw = hs + NOBJ_ * C;           // 36*RAWP  ([j][i])
    float* als = raw + NOBJ_ * RAWP;       // 36
    float* ald = als + NOBJ_;              // 36
    float* mj  = ald + NOBJ_;              // 36
    float* inv = mj + NOBJ_;               // 36

    const int head = blockIdx.x;
    const int b    = blockIdx.y;
    const int tid  = threadIdx.x;
    const int rowstride = HEADS * C;

    // load the 36 x C head-slice into smem (vectorized)
#pragma unroll
    for (int idx = tid * 4; idx < NOBJ_ * C; idx += 256 * 4) {
        const int i = idx / C, c = idx % C;
        *(float4*)&hs[idx] =
            *(const float4*)&h[(size_t)(b * NOBJ_ + i) * rowstride + head * C + c];
    }
    __syncthreads();

    // per-node attention logits: warp-per-row dot products
    const int warp = tid >> 5, lane = tid & 31;
    for (int i = warp; i < NOBJ_; i += 8) {
        float s = 0.f, d = 0.f;
#pragma unroll
        for (int c = lane; c < C; c += 32) {
            const float hv = hs[i * C + c];
            s += hv * a_src[head * C + c];
            d += hv * a_dst[head * C + c];
        }
#pragma unroll
        for (int o = 16; o > 0; o >>= 1) {
            s += __shfl_down_sync(0xFFFFFFFFu, s, o);
            d += __shfl_down_sync(0xFFFFFFFFu, d, o);
        }
        if (lane == 0) { als[i] = s; ald[i] = d; }
    }
    __syncthreads();

    // raw logits, [j][i] layout (parallel over all 1296 pairs)
    for (int idx = tid; idx < NOBJ_ * NOBJ_; idx += 256) {
        const int j = idx / NOBJ_, i = idx - j * NOBJ_;
        float x = als[i] + ald[j];
        raw[j * RAWP + i] = x > 0.f ? x : 0.2f * x;
    }
    __syncthreads();

    // per-destination max
    if (tid < NOBJ_) {
        float m = -1e30f;
#pragma unroll
        for (int i = 0; i < NOBJ_; i++) m = fmaxf(m, raw[tid * RAWP + i]);
        mj[tid] = m;
    }
    __syncthreads();

    // exp (parallel)
    for (int idx = tid; idx < NOBJ_ * NOBJ_; idx += 256) {
        const int j = idx / NOBJ_, i = idx - j * NOBJ_;
        raw[j * RAWP + i] = __expf(raw[j * RAWP + i] - mj[j]);
    }
    __syncthreads();

    // per-destination sum -> inverse
    if (tid < NOBJ_) {
        float s = 0.f;
#pragma unroll
        for (int i = 0; i < NOBJ_; i++) s += raw[tid * RAWP + i];
        inv[tid] = 1.0f / (s + 1e-16f);
    }
    __syncthreads();

    // aggregation: out[j, c4] = inv[j] * sum_i raw[j][i] * hs[i][c4]  (float4)
    const int QC = C / 4;
    for (int qidx = tid; qidx < NOBJ_ * QC; qidx += 256) {
        const int j = qidx / QC, c4 = qidx - j * QC;
        const float* rj = raw + j * RAWP;
        float4 acc = make_float4(0.f, 0.f, 0.f, 0.f);
#pragma unroll
        for (int i = 0; i < NOBJ_; i++) {
            const float a = rj[i];
            const float4 hv = *(const float4*)&hs[i * C + c4 * 4];
            acc.x += a * hv.x; acc.y += a * hv.y;
            acc.z += a * hv.z; acc.w += a * hv.w;
        }
        const float vj = inv[j];
        acc.x *= vj; acc.y *= vj; acc.z *= vj; acc.w *= vj;

        const int c = c4 * 4;
        const size_t o = (size_t)(b * NOBJ_ + j) * rowstride + head * C + c;
        if (MODE == 2) {
            *(float4*)&out[o] = acc;
        } else {
            const float4 bv = *(const float4*)&bias[head * C + c];
            float4 v = make_float4(acc.x + bv.x, acc.y + bv.y, acc.z + bv.z, acc.w + bv.w);
            v.x = v.x > 0.f ? v.x : 0.f;  v.y = v.y > 0.f ? v.y : 0.f;
            v.z = v.z > 0.f ? v.z : 0.f;  v.w = v.w > 0.f ? v.w : 0.f;
            if (MODE == 0) *(float4*)&out[o] = v;
            if (MODE == 1) {
                const float4 rv = *(const float4*)&res[o];
                v.x += rv.x; v.y += rv.y; v.z += rv.z; v.w += rv.w;
            }
            bf16 h0, l0, h1, l1, h2, l2, h3, l3;
            split_bf16(v.x, h0, l0); split_bf16(v.y, h1, l1);
            split_bf16(v.z, h2, l2); split_bf16(v.w, h3, l3);
            *(__nv_bfloat162*)&outH[o]     = __nv_bfloat162(h0, h1);
            *(__nv_bfloat162*)&outH[o + 2] = __nv_bfloat162(h2, h3);
            *(__nv_bfloat162*)&outL[o]     = __nv_bfloat162(l0, l1);
            *(__nv_bfloat162*)&outL[o + 2] = __nv_bfloat162(l2, l3);
        }
    }
}

// ---------------- layer-3 mean over heads + bias --------------------------------
__global__ __launch_bounds__(256) void mean_bias_kernel(
    const float* __restrict__ scr, const float* __restrict__ b3, float* __restrict__ out)
{
    const int idx = blockIdx.x * blockDim.x + threadIdx.x;
    if (idx >= NNODES * 512) return;
    const int n = idx / 512, c = idx % 512;
    float s = 0.f;
#pragma unroll
    for (int hd = 0; hd < 5; hd++) s += scr[(size_t)n * 2560 + hd * 512 + c];
    out[idx] = s * 0.2f + b3[c];
}

// ------------------------------- launch ------------------------------------------
template <typename T>
static T* sym_addr(const void* symbol)
{
    void* p = nullptr;
    cudaGetSymbolAddress(&p, symbol);
    return (T*)p;
}

extern "C" void kernel_launch(void* const* d_in, const int* in_sizes, int n_in,
                              void* d_out, int out_size)
{
    (void)in_sizes; (void)n_in; (void)out_size;
    const float* qe   = (const float*)d_in[0];
    const float* obj  = (const float*)d_in[1];
    // d_in[2] = edge_index (ignored: graph fully-connected per image)
    const float* Wq   = (const float*)d_in[3];
    const float* bq   = (const float*)d_in[4];
    const float* Wv   = (const float*)d_in[5];
    const float* bv   = (const float*)d_in[6];
    const float* W1   = (const float*)d_in[7];
    const float* a1s  = (const float*)d_in[8];
    const float* a1d  = (const float*)d_in[9];
    const float* b1   = (const float*)d_in[10];
    const float* W2   = (const float*)d_in[11];
    const float* a2s  = (const float*)d_in[12];
    const float* a2d  = (const float*)d_in[13];
    const float* b2   = (const float*)d_in[14];
    const float* W3   = (const float*)d_in[15];
    const float* a3s  = (const float*)d_in[16];
    const float* a3d  = (const float*)d_in[17];
    const float* b3   = (const float*)d_in[18];
    float* out = (float*)d_out;

    float* dq   = sym_addr<float>(g_q);
    float* dh   = sym_addr<float>(g_h);
    float* dg1  = sym_addr<float>(g_g1);
    float* da3  = sym_addr<float>(g_a3);
    bf16* qe_h  = sym_addr<bf16>(g_qe_h);   bf16* qe_l  = sym_addr<bf16>(g_qe_l);
    bf16* obj_h = sym_addr<bf16>(g_obj_h);  bf16* obj_l = sym_addr<bf16>(g_obj_l);
    bf16* x_h   = sym_addr<bf16>(g_x_h);    bf16* x_l   = sym_addr<bf16>(g_x_l);
    bf16* g1_h  = sym_addr<bf16>(g_g1_h);   bf16* g1_l  = sym_addr<bf16>(g_g1_l);
    bf16* g2_h  = sym_addr<bf16>(g_g2_h);   bf16* g2_l  = sym_addr<bf16>(g_g2_l);
    bf16* wq_h  = sym_addr<bf16>(g_Wq_hi);  bf16* wq_l  = sym_addr<bf16>(g_Wq_lo);
    bf16* wv_h  = sym_addr<bf16>(g_Wv_hi);  bf16* wv_l  = sym_addr<bf16>(g_Wv_lo);
    bf16* w1_h  = sym_addr<bf16>(g_W1_hi);  bf16* w1_l  = sym_addr<bf16>(g_W1_lo);
    bf16* w2_h  = sym_addr<bf16>(g_W2_hi);  bf16* w2_l  = sym_addr<bf16>(g_W2_lo);
    bf16* w3_h  = sym_addr<bf16>(g_W3_hi);  bf16* w3_l  = sym_addr<bf16>(g_W3_lo);

    cudaFuncSetAttribute(hgemm, cudaFuncAttributeMaxDynamicSharedMemorySize, GEMM_SMEM);
    const int smem12 = (NOBJ_ * 256 + NOBJ_ * RAWP + 4 * NOBJ_) * sizeof(float);
    const int smem3  = (NOBJ_ * 512 + NOBJ_ * RAWP + 4 * NOBJ_) * sizeof(float);
    cudaFuncSetAttribute(gat_attn<5, 512, 2>, cudaFuncAttributeMaxDynamicSharedMemorySize, smem3);

    // single stream, R9 order, split-K x19 q-GEMM
    // 1) conv qe
    conv_pair<<<dim3((KPAD_Q / 4 + 255) / 256, BIMG), 256>>>(qe, qe_h, qe_l, QD_, KPAD_Q);
    // 2) prep Wq
    prep_w<<<dim3(2048 / 32, KPAD_Q / 32), dim3(32, 8)>>>(QD_, 2048, KPAD_Q, Wq, wq_h, wq_l);
    // 3) zero q accumulator
    zero_kernel<<<(BIMG * 2048 + 255) / 256, 256>>>(dq, BIMG * 2048);
    // 4) q_raw = qe @ Wq (split-K x19, atomicAdd)   [128, 2048]
    hgemm<<<dim3(2048 / BN, 1, 19), GEMM_THREADS, GEMM_SMEM>>>(
        2048, KPAD_Q, (KPAD_Q / BK) / 19, qe_h, qe_l, wq_h, wq_l,
        dq, nullptr, nullptr, nullptr, nullptr, nullptr, 3);
    // 5) conv obj
    conv_pair<<<dim3((2048 / 4 + 255) / 256, NNODES), 256>>>(obj, obj_h, obj_l, VD_, 2048);
    // 6) prep Wv
    prep_w<<<dim3(2048 / 32, 2048 / 32), dim3(32, 8)>>>(2048, 2048, 2048, Wv, wv_h, wv_l);
    // 7) x = (obj @ Wv + bv) * (q_raw + bq) -> bf16 pair  [4608, 2048]
    hgemm<<<dim3(2048 / BN, NNODES / BM), GEMM_THREADS, GEMM_SMEM>>>(
        2048, 2048, 2048 / BK, obj_h, obj_l, wv_h, wv_l,
        nullptr, x_h, x_l, bv, dq, bq, 2);
    // 8) prep W1
    prep_w<<<dim3(1024 / 32, 2048 / 32), dim3(32, 8)>>>(2048, 1024, 2048, W1, w1_h, w1_l);
    // 9) h1 = x @ W1                     [4608, 1024]
    hgemm<<<dim3(1024 / BN, NNODES / BM), GEMM_THREADS, GEMM_SMEM>>>(
        1024, 2048, 2048 / BK, x_h, x_l, w1_h, w1_l,
        dh, nullptr, nullptr, nullptr, nullptr, nullptr, 0);
    // 10) prep W2
    prep_w<<<dim3(1024 / 32, 1024 / 32), dim3(32, 8)>>>(1024, 1024, 1024, W2, w2_h, w2_l);
    // 11) g1 = relu(attn1 + b1)          fp32 + pair
    gat_attn<4, 256, 0><<<dim3(4, BIMG), 256, smem12>>>(dh, a1s, a1d, b1, nullptr, dg1, g1_h, g1_l);
    // 12) h2 = g1 @ W2                   [4608, 1024]
    hgemm<<<dim3(1024 / BN, NNODES / BM), GEMM_THREADS, GEMM_SMEM>>>(
        1024, 1024, 1024 / BK, g1_h, g1_l, w2_h, w2_l,
        dh, nullptr, nullptr, nullptr, nullptr, nullptr, 0);
    // 13) prep W3
    prep_w<<<dim3(2560 / 32, 1024 / 32), dim3(32, 8)>>>(1024, 2560, 1024, W3, w3_h, w3_l);
    // 14) g2 = relu(attn2 + b2) + g1     pair only
    gat_attn<4, 256, 1><<<dim3(4, BIMG), 256, smem12>>>(dh, a2s, a2d, b2, dg1, nullptr, g2_h, g2_l);
    // 15) h3 = g2 @ W3                   [4608, 2560]
    hgemm<<<dim3(2560 / BN, NNODES / BM), GEMM_THREADS, GEMM_SMEM>>>(
        2560, 1024, 1024 / BK, g2_h, g2_l, w3_h, w3_l,
        dh, nullptr, nullptr, nullptr, nullptr, nullptr, 0);
    // 16) per-head aggregation -> scratch [4608, 5, 512]
    gat_attn<5, 512, 2><<<dim3(5, BIMG), 256, smem3>>>(dh, a3s, a3d, nullptr, nullptr, da3, nullptr, nullptr);
    // 17) mean over heads + b3 -> output  [4608, 512]
    mean_bias_kernel<<<(NNODES * 512 + 255) / 256, 256>>>(da3, b3, out);
}

// round 15
// speedup vs baseline: 1.5402x; 1.5402x over previous
#include <cuda_runtime.h>
#include <cuda_bf16.h>
#include <cstdint>

// Problem constants
#define BIMG   128
#define NOBJ_  36
#define NNODES (BIMG * NOBJ_)   // 4608
#define QD_    2400
#define VD_    2048
#define KPAD_Q 2432             // 2400 padded to multiple of 32

typedef __nv_bfloat16 bf16;

// ---------------- scratch (device globals; no allocation allowed) -------------
__device__ float g_q  [BIMG   * 2048];          // q fp32 (split-K accumulated)
__device__ float g_h  [NNODES * 2560];          // h1/h2/h3 (fp32, attention input)
__device__ float g_g1 [NNODES * 1024];          // g1 fp32 (residual)
__device__ float g_a3 [NNODES * 2560];          // layer-3 per-head agg

__device__ bf16 g_qe_h [BIMG * KPAD_Q],  g_qe_l [BIMG * KPAD_Q];
__device__ bf16 g_obj_h[NNODES * 2048],  g_obj_l[NNODES * 2048];
__device__ bf16 g_x_h  [NNODES * 2048],  g_x_l  [NNODES * 2048];
__device__ bf16 g_g1_h [NNODES * 1024],  g_g1_l [NNODES * 1024];
__device__ bf16 g_g2_h [NNODES * 1024],  g_g2_l [NNODES * 1024];

// weights transposed to [N, Kpad], split into bf16 hi/lo
__device__ bf16 g_Wq_hi[2048 * KPAD_Q], g_Wq_lo[2048 * KPAD_Q];
__device__ bf16 g_Wv_hi[2048 * 2048],   g_Wv_lo[2048 * 2048];
__device__ bf16 g_W1_hi[1024 * 2048],   g_W1_lo[1024 * 2048];
__device__ bf16 g_W2_hi[1024 * 1024],   g_W2_lo[1024 * 1024];
__device__ bf16 g_W3_hi[2560 * 1024],   g_W3_lo[2560 * 1024];

// ---------------- small helpers -------------------------------------------------
__device__ __forceinline__ uint32_t smem_u32(const void* p) {
    uint32_t a;
    asm("{ .reg .u64 t; cvta.to.shared.u64 t, %1; cvt.u32.u64 %0, t; }" : "=r"(a) : "l"(p));
    return a;
}
__device__ __forceinline__ void cp_async16(uint32_t dst, const void* src) {
    asm volatile("cp.async.cg.shared.global [%0], [%1], 16;" :: "r"(dst), "l"(src));
}
__device__ __forceinline__ void cp_commit() { asm volatile("cp.async.commit_group;"); }
__device__ __forceinline__ void ldm_x4(uint32_t* r, uint32_t addr) {
    asm volatile("ldmatrix.sync.aligned.m8n8.x4.shared.b16 {%0,%1,%2,%3}, [%4];"
                 : "=r"(r[0]), "=r"(r[1]), "=r"(r[2]), "=r"(r[3]) : "r"(addr));
}
__device__ __forceinline__ void mma16816(float* c, const uint32_t* a, uint32_t b0, uint32_t b1) {
    asm volatile("mma.sync.aligned.m16n8k16.row.col.f32.bf16.bf16.f32 "
                 "{%0,%1,%2,%3}, {%4,%5,%6,%7}, {%8,%9}, {%0,%1,%2,%3};"
                 : "+f"(c[0]), "+f"(c[1]), "+f"(c[2]), "+f"(c[3])
                 : "r"(a[0]), "r"(a[1]), "r"(a[2]), "r"(a[3]), "r"(b0), "r"(b1));
}
__device__ __forceinline__ void split_bf16(float v, bf16& h, bf16& l) {
    h = __float2bfloat16(v);
    l = __float2bfloat16(v - __bfloat162float(h));
}

// ---------------- weight prep: W[K,N] fp32 -> Wt_hi/lo [N,Kpad] bf16 ------------
__global__ __launch_bounds__(256) void prep_w(
    int K, int N, int Kpad, const float* __restrict__ W,
    bf16* __restrict__ hi, bf16* __restrict__ lo)
{
    __shared__ float t[32][33];
    const int n0 = blockIdx.x * 32, k0 = blockIdx.y * 32;
    const int tx = threadIdx.x, ty = threadIdx.y;   // 32 x 8
#pragma unroll
    for (int i = 0; i < 4; i++) {
        const int k = k0 + ty + i * 8;
        t[ty + i * 8][tx] = (k < K) ? W[(size_t)k * N + n0 + tx] : 0.f;
    }
    __syncthreads();
#pragma unroll
    for (int i = 0; i < 4; i++) {
        const int n = n0 + ty + i * 8;
        const float v = t[tx][ty + i * 8];
        bf16 h, l; split_bf16(v, h, l);
        hi[(size_t)n * Kpad + k0 + tx] = h;
        lo[(size_t)n * Kpad + k0 + tx] = l;
    }
}

// ---------------- activation conv: fp32 [M,K] -> bf16 hi/lo [M,Kpad] ------------
__global__ __launch_bounds__(256) void conv_pair(
    const float* __restrict__ src, bf16* __restrict__ hi, bf16* __restrict__ lo,
    int K, int Kpad)
{
    const int c4 = blockIdx.x * blockDim.x + threadIdx.x;
    if (c4 * 4 >= Kpad) return;
    const int r = blockIdx.y;
    float4 v;
    if (c4 * 4 + 4 <= K) v = *(const float4*)&src[(size_t)r * K + c4 * 4];
    else                 v = make_float4(0.f, 0.f, 0.f, 0.f);
    bf16 h0, l0, h1, l1, h2, l2, h3, l3;
    split_bf16(v.x, h0, l0); split_bf16(v.y, h1, l1);
    split_bf16(v.z, h2, l2); split_bf16(v.w, h3, l3);
    const size_t o = (size_t)r * Kpad + c4 * 4;
    *(__nv_bfloat162*)&hi[o]     = __nv_bfloat162(h0, h1);
    *(__nv_bfloat162*)&hi[o + 2] = __nv_bfloat162(h2, h3);
    *(__nv_bfloat162*)&lo[o]     = __nv_bfloat162(l0, l1);
    *(__nv_bfloat162*)&lo[o + 2] = __nv_bfloat162(l2, l3);
}

// ---------------- zero-fill -----------------------------------------------------
__global__ __launch_bounds__(256) void zero_kernel(float* __restrict__ p, int n)
{
    const int i = blockIdx.x * blockDim.x + threadIdx.x;
    if (i < n) p[i] = 0.f;
}

// ---------------- HMMA bf16x3 GEMM (R9 shape: 256 thr, 2x4 warps, 64x32) --------
// C[M,N] = A[M,K] @ Bt[N,K]^T where A,Bt are hi/lo bf16 splits.
// mode 0: C = acc (fp32)
// mode 2: (acc + bias) * (qmat[row/36] + qbias)  -> Chi/Clo bf16 pair
// mode 3: atomicAdd into C (split-K accumulation; grid.z = #chunks, nk iters each)
#define BM 128
#define BN 128
#define BK 32
#define GEMM_THREADS 256
#define KSTRIDE 40                     // padded smem row stride (bf16 elems)
#define MAT_BYTES (BM * KSTRIDE * 2)   // 10240
#define STAGE_BYTES (4 * MAT_BYTES)    // Ah, Al, Bh, Bl
#define GEMM_SMEM (2 * STAGE_BYTES)    // 81920

__global__ __launch_bounds__(GEMM_THREADS, 2) void hgemm(
    int N, int K, int nk,
    const bf16* __restrict__ Ah, const bf16* __restrict__ Al,
    const bf16* __restrict__ Bh, const bf16* __restrict__ Bl,
    float* __restrict__ C, bf16* __restrict__ Chi, bf16* __restrict__ Clo,
    const float* __restrict__ bias, const float* __restrict__ qmat,
    const float* __restrict__ qbias, int mode)
{
    extern __shared__ __align__(128) char smem[];
    const uint32_t sbase = smem_u32(smem);
    const int tid = threadIdx.x, wid = tid >> 5, lane = tid & 31;
    const int warp_m = wid >> 2, warp_n = wid & 3;       // 2 x 4 warps
    const int brow = blockIdx.y * BM, bcol = blockIdx.x * BN;
    const int k_begin = blockIdx.z * nk * BK;

    float acc[4][4][4];
#pragma unroll
    for (int m = 0; m < 4; m++)
#pragma unroll
        for (int n = 0; n < 4; n++)
#pragma unroll
            for (int e = 0; e < 4; e++) acc[m][n][e] = 0.f;

    // ---- gmem -> smem stage loader (cp.async, 16B granules) ----
    auto load_stage = [&](int buf, int k0) {
        const uint32_t s = sbase + buf * STAGE_BYTES;
#pragma unroll
        for (int it = 0; it < 2; it++) {
            const int idx = tid + it * 256;       // 0..511
            const int r = idx >> 2, c = (idx & 3) * 8;
            const uint32_t so = (uint32_t)(r * KSTRIDE + c) * 2;
            const size_t ga = (size_t)(brow + r) * K + k0 + c;
            const size_t gb = (size_t)(bcol + r) * K + k0 + c;
            cp_async16(s + so,                 Ah + ga);
            cp_async16(s + MAT_BYTES + so,     Al + ga);
            cp_async16(s + 2 * MAT_BYTES + so, Bh + gb);
            cp_async16(s + 3 * MAT_BYTES + so, Bl + gb);
        }
        cp_commit();
    };

    load_stage(0, k_begin);
    if (nk > 1) load_stage(1, k_begin + BK);
    else        cp_commit();

    // ldmatrix lane addressing (byte offsets within a matrix)
    const int a_row = lane & 15, a_k8 = (lane >> 4) * 8;
    const uint32_t aoff = (uint32_t)((warp_m * 64 + a_row) * KSTRIDE + a_k8) * 2;
    const int bmat = lane >> 3, brl = lane & 7;
    const int b_n = warp_n * 32 + (bmat >> 1) * 8 + brl;
    const int b_k = (bmat & 1) * 8;
    const uint32_t boff = (uint32_t)(b_n * KSTRIDE + b_k) * 2;

    for (int kt = 0; kt < nk; kt++) {
        asm volatile("cp.async.wait_group 1;");
        __syncthreads();

        const uint32_t s = sbase + (kt & 1) * STAGE_BYTES;
        const uint32_t sAh = s + aoff;
        const uint32_t sAl = sAh + MAT_BYTES;
        const uint32_t sBh = s + 2 * MAT_BYTES + boff;
        const uint32_t sBl = sBh + MAT_BYTES;

#pragma unroll
        for (int ks = 0; ks < 2; ks++) {
            uint32_t ah[4][4], al[4][4];
#pragma unroll
            for (int m = 0; m < 4; m++) {
                const uint32_t o = (uint32_t)(m * 16 * KSTRIDE + ks * 16) * 2;
                ldm_x4(ah[m], sAh + o);
                ldm_x4(al[m], sAl + o);
            }
#pragma unroll
            for (int np = 0; np < 2; np++) {
                uint32_t bh[4], bl[4];
                const uint32_t o = (uint32_t)(np * 16 * KSTRIDE + ks * 16) * 2;
                ldm_x4(bh, sBh + o);
                ldm_x4(bl, sBl + o);
#pragma unroll
                for (int m = 0; m < 4; m++)
#pragma unroll
                    for (int nsel = 0; nsel < 2; nsel++) {
                        float* a4 = acc[m][np * 2 + nsel];
                        mma16816(a4, ah[m], bh[nsel * 2], bh[nsel * 2 + 1]);
                        mma16816(a4, al[m], bh[nsel * 2], bh[nsel * 2 + 1]);
                        mma16816(a4, ah[m], bl[nsel * 2], bl[nsel * 2 + 1]);
                    }
            }
        }
        __syncthreads();

        const int kn = kt + 2;
        if (kn < nk) load_stage(kn & 1, k_begin + kn * BK);
        else         cp_commit();   // keep group accounting aligned
    }
    asm volatile("cp.async.wait_group 0;");

    // ---- epilogue (register -> gmem direct) ----
#pragma unroll
    for (int m = 0; m < 4; m++) {
        const int r0 = brow + warp_m * 64 + m * 16 + (lane >> 2);
#pragma unroll
        for (int n = 0; n < 4; n++) {
            const int col = bcol + warp_n * 32 + n * 8 + (lane & 3) * 2;
#pragma unroll
            for (int half = 0; half < 2; half++) {
                const int row = r0 + half * 8;
                float v0 = acc[m][n][half * 2 + 0];
                float v1 = acc[m][n][half * 2 + 1];
                if (mode == 2) {
                    const size_t qo = (size_t)(row / NOBJ_) * N + col;
                    v0 = (v0 + bias[col])     * (qmat[qo]     + qbias[col]);
                    v1 = (v1 + bias[col + 1]) * (qmat[qo + 1] + qbias[col + 1]);
                    bf16 h0, l0, h1, l1;
                    split_bf16(v0, h0, l0); split_bf16(v1, h1, l1);
                    *(__nv_bfloat162*)&Chi[(size_t)row * N + col] = __nv_bfloat162(h0, h1);
                    *(__nv_bfloat162*)&Clo[(size_t)row * N + col] = __nv_bfloat162(l0, l1);
                } else if (mode == 3) {
                    atomicAdd(&C[(size_t)row * N + col],     v0);
                    atomicAdd(&C[(size_t)row * N + col + 1], v1);
                } else {
                    *(float2*)&C[(size_t)row * N + col] = make_float2(v0, v1);
                }
            }
        }
    }
}

// ---------------- per-(image, head) dense GAT attention -------------------------
// MODE 0: g = relu(agg+bias); out fp32 + hi/lo pair
// MODE 1: g = relu(agg+bias) + res; out hi/lo pair only
// MODE 2: out = agg (fp32 only)
#define RAWP 37
template <int HEADS, int C, int MODE>
__global__ __launch_bounds__(256) void gat_attn(
    const float* __restrict__ h,
    const float* __restrict__ a_src, const float* __restrict__ a_dst,
    const float* __restrict__ bias,  const float* __restrict__ res,
    float* __restrict__ out, bf16* __restrict__ outH, bf16* __restrict__ outL)
{
    extern __shared__ float sm[];
    float* hs  = sm;                       // 36*C
    float* raw = hs + NOBJ_ * C;           // 36*RAWP  ([j][i])
    float* als = raw + NOBJ_ * RAWP;       // 36
    float* ald = als + NOBJ_;              // 36
    float* mj  = ald + NOBJ_;              // 36
    float* inv = mj + NOBJ_;               // 36

    const int head = blockIdx.x;
    const int b    = blockIdx.y;
    const int tid  = threadIdx.x;
    const int rowstride = HEADS * C;

    // load the 36 x C head-slice into smem (vectorized)
#pragma unroll
    for (int idx = tid * 4; idx < NOBJ_ * C; idx += 256 * 4) {
        const int i = idx / C, c = idx % C;
        *(float4*)&hs[idx] =
            *(const float4*)&h[(size_t)(b * NOBJ_ + i) * rowstride + head * C + c];
    }
    __syncthreads();

    // per-node attention logits: warp-per-row dot products
    const int warp = tid >> 5, lane = tid & 31;
    for (int i = warp; i < NOBJ_; i += 8) {
        float s = 0.f, d = 0.f;
#pragma unroll
        for (int c = lane; c < C; c += 32) {
            const float hv = hs[i * C + c];
            s += hv * a_src[head * C + c];
            d += hv * a_dst[head * C + c];
        }
#pragma unroll
        for (int o = 16; o > 0; o >>= 1) {
            s += __shfl_down_sync(0xFFFFFFFFu, s, o);
            d += __shfl_down_sync(0xFFFFFFFFu, d, o);
        }
        if (lane == 0) { als[i] = s; ald[i] = d; }
    }
    __syncthreads();

    // raw logits, [j][i] layout (parallel over all 1296 pairs)
    for (int idx = tid; idx < NOBJ_ * NOBJ_; idx += 256) {
        const int j = idx / NOBJ_, i = idx - j * NOBJ_;
        float x = als[i] + ald[j];
        raw[j * RAWP + i] = x > 0.f ? x : 0.2f * x;
    }
    __syncthreads();

    // per-destination max
    if (tid < NOBJ_) {
        float m = -1e30f;
#pragma unroll
        for (int i = 0; i < NOBJ_; i++) m = fmaxf(m, raw[tid * RAWP + i]);
        mj[tid] = m;
    }
    __syncthreads();

    // exp (parallel)
    for (int idx = tid; idx < NOBJ_ * NOBJ_; idx += 256) {
        const int j = idx / NOBJ_, i = idx - j * NOBJ_;
        raw[j * RAWP + i] = __expf(raw[j * RAWP + i] - mj[j]);
    }
    __syncthreads();

    // per-destination sum -> inverse
    if (tid < NOBJ_) {
        float s = 0.f;
#pragma unroll
        for (int i = 0; i < NOBJ_; i++) s += raw[tid * RAWP + i];
        inv[tid] = 1.0f / (s + 1e-16f);
    }
    __syncthreads();

    // aggregation: out[j, c4] = inv[j] * sum_i raw[j][i] * hs[i][c4]  (float4)
    const int QC = C / 4;
    for (int qidx = tid; qidx < NOBJ_ * QC; qidx += 256) {
        const int j = qidx / QC, c4 = qidx - j * QC;
        const float* rj = raw + j * RAWP;
        float4 acc = make_float4(0.f, 0.f, 0.f, 0.f);
#pragma unroll
        for (int i = 0; i < NOBJ_; i++) {
            const float a = rj[i];
            const float4 hv = *(const float4*)&hs[i * C + c4 * 4];
            acc.x += a * hv.x; acc.y += a * hv.y;
            acc.z += a * hv.z; acc.w += a * hv.w;
        }
        const float vj = inv[j];
        acc.x *= vj; acc.y *= vj; acc.z *= vj; acc.w *= vj;

        const int c = c4 * 4;
        const size_t o = (size_t)(b * NOBJ_ + j) * rowstride + head * C + c;
        if (MODE == 2) {
            *(float4*)&out[o] = acc;
        } else {
            const float4 bv = *(const float4*)&bias[head * C + c];
            float4 v = make_float4(acc.x + bv.x, acc.y + bv.y, acc.z + bv.z, acc.w + bv.w);
            v.x = v.x > 0.f ? v.x : 0.f;  v.y = v.y > 0.f ? v.y : 0.f;
            v.z = v.z > 0.f ? v.z : 0.f;  v.w = v.w > 0.f ? v.w : 0.f;
            if (MODE == 0) *(float4*)&out[o] = v;
            if (MODE == 1) {
                const float4 rv = *(const float4*)&res[o];
                v.x += rv.x; v.y += rv.y; v.z += rv.z; v.w += rv.w;
            }
            bf16 h0, l0, h1, l1, h2, l2, h3, l3;
            split_bf16(v.x, h0, l0); split_bf16(v.y, h1, l1);
            split_bf16(v.z, h2, l2); split_bf16(v.w, h3, l3);
            *(__nv_bfloat162*)&outH[o]     = __nv_bfloat162(h0, h1);
            *(__nv_bfloat162*)&outH[o + 2] = __nv_bfloat162(h2, h3);
            *(__nv_bfloat162*)&outL[o]     = __nv_bfloat162(l0, l1);
            *(__nv_bfloat162*)&outL[o + 2] = __nv_bfloat162(l2, l3);
        }
    }
}

// ---------------- layer-3 mean over heads + bias --------------------------------
__global__ __launch_bounds__(256) void mean_bias_kernel(
    const float* __restrict__ scr, const float* __restrict__ b3, float* __restrict__ out)
{
    const int idx = blockIdx.x * blockDim.x + threadIdx.x;
    if (idx >= NNODES * 512) return;
    const int n = idx / 512, c = idx % 512;
    float s = 0.f;
#pragma unroll
    for (int hd = 0; hd < 5; hd++) s += scr[(size_t)n * 2560 + hd * 512 + c];
    out[idx] = s * 0.2f + b3[c];
}

// ------------------------------- launch ------------------------------------------
template <typename T>
static T* sym_addr(const void* symbol)
{
    void* p = nullptr;
    cudaGetSymbolAddress(&p, symbol);
    return (T*)p;
}

extern "C" void kernel_launch(void* const* d_in, const int* in_sizes, int n_in,
                              void* d_out, int out_size)
{
    (void)in_sizes; (void)n_in; (void)out_size;
    const float* qe   = (const float*)d_in[0];
    const float* obj  = (const float*)d_in[1];
    // d_in[2] = edge_index (ignored: graph fully-connected per image)
    const float* Wq   = (const float*)d_in[3];
    const float* bq   = (const float*)d_in[4];
    const float* Wv   = (const float*)d_in[5];
    const float* bv   = (const float*)d_in[6];
    const float* W1   = (const float*)d_in[7];
    const float* a1s  = (const float*)d_in[8];
    const float* a1d  = (const float*)d_in[9];
    const float* b1   = (const float*)d_in[10];
    const float* W2   = (const float*)d_in[11];
    const float* a2s  = (const float*)d_in[12];
    const float* a2d  = (const float*)d_in[13];
    const float* b2   = (const float*)d_in[14];
    const float* W3   = (const float*)d_in[15];
    const float* a3s  = (const float*)d_in[16];
    const float* a3d  = (const float*)d_in[17];
    const float* b3   = (const float*)d_in[18];
    float* out = (float*)d_out;

    float* dq   = sym_addr<float>(g_q);
    float* dh   = sym_addr<float>(g_h);
    float* dg1  = sym_addr<float>(g_g1);
    float* da3  = sym_addr<float>(g_a3);
    bf16* qe_h  = sym_addr<bf16>(g_qe_h);   bf16* qe_l  = sym_addr<bf16>(g_qe_l);
    bf16* obj_h = sym_addr<bf16>(g_obj_h);  bf16* obj_l = sym_addr<bf16>(g_obj_l);
    bf16* x_h   = sym_addr<bf16>(g_x_h);    bf16* x_l   = sym_addr<bf16>(g_x_l);
    bf16* g1_h  = sym_addr<bf16>(g_g1_h);   bf16* g1_l  = sym_addr<bf16>(g_g1_l);
    bf16* g2_h  = sym_addr<bf16>(g_g2_h);   bf16* g2_l  = sym_addr<bf16>(g_g2_l);
    bf16* wq_h  = sym_addr<bf16>(g_Wq_hi);  bf16* wq_l  = sym_addr<bf16>(g_Wq_lo);
    bf16* wv_h  = sym_addr<bf16>(g_Wv_hi);  bf16* wv_l  = sym_addr<bf16>(g_Wv_lo);
    bf16* w1_h  = sym_addr<bf16>(g_W1_hi);  bf16* w1_l  = sym_addr<bf16>(g_W1_lo);
    bf16* w2_h  = sym_addr<bf16>(g_W2_hi);  bf16* w2_l  = sym_addr<bf16>(g_W2_lo);
    bf16* w3_h  = sym_addr<bf16>(g_W3_hi);  bf16* w3_l  = sym_addr<bf16>(g_W3_lo);

    cudaFuncSetAttribute(hgemm, cudaFuncAttributeMaxDynamicSharedMemorySize, GEMM_SMEM);
    const int smem12 = (NOBJ_ * 256 + NOBJ_ * RAWP + 4 * NOBJ_) * sizeof(float);
    const int smem3  = (NOBJ_ * 512 + NOBJ_ * RAWP + 4 * NOBJ_) * sizeof(float);
    cudaFuncSetAttribute(gat_attn<5, 512, 2>, cudaFuncAttributeMaxDynamicSharedMemorySize, smem3);

    // single stream, R9 order, split-K x19 q-GEMM
    // 1) conv qe
    conv_pair<<<dim3((KPAD_Q / 4 + 255) / 256, BIMG), 256>>>(qe, qe_h, qe_l, QD_, KPAD_Q);
    // 2) prep Wq
    prep_w<<<dim3(2048 / 32, KPAD_Q / 32), dim3(32, 8)>>>(QD_, 2048, KPAD_Q, Wq, wq_h, wq_l);
    // 3) zero q accumulator
    zero_kernel<<<(BIMG * 2048 + 255) / 256, 256>>>(dq, BIMG * 2048);
    // 4) q_raw = qe @ Wq (split-K x19, atomicAdd)   [128, 2048]
    hgemm<<<dim3(2048 / BN, 1, 19), GEMM_THREADS, GEMM_SMEM>>>(
        2048, KPAD_Q, (KPAD_Q / BK) / 19, qe_h, qe_l, wq_h, wq_l,
        dq, nullptr, nullptr, nullptr, nullptr, nullptr, 3);
    // 5) conv obj
    conv_pair<<<dim3((2048 / 4 + 255) / 256, NNODES), 256>>>(obj, obj_h, obj_l, VD_, 2048);
    // 6) prep Wv
    prep_w<<<dim3(2048 / 32, 2048 / 32), dim3(32, 8)>>>(2048, 2048, 2048, Wv, wv_h, wv_l);
    // 7) x = (obj @ Wv + bv) * (q_raw + bq) -> bf16 pair  [4608, 2048]
    hgemm<<<dim3(2048 / BN, NNODES / BM), GEMM_THREADS, GEMM_SMEM>>>(
        2048, 2048, 2048 / BK, obj_h, obj_l, wv_h, wv_l,
        nullptr, x_h, x_l, bv, dq, bq, 2);
    // 8) prep W1
    prep_w<<<dim3(1024 / 32, 2048 / 32), dim3(32, 8)>>>(2048, 1024, 2048, W1, w1_h, w1_l);
    // 9) h1 = x @ W1                     [4608, 1024]
    hgemm<<<dim3(1024 / BN, NNODES / BM), GEMM_THREADS, GEMM_SMEM>>>(
        1024, 2048, 2048 / BK, x_h, x_l, w1_h, w1_l,
        dh, nullptr, nullptr, nullptr, nullptr, nullptr, 0);
    // 10) prep W2
    prep_w<<<dim3(1024 / 32, 1024 / 32), dim3(32, 8)>>>(1024, 1024, 1024, W2, w2_h, w2_l);
    // 11) g1 = relu(attn1 + b1)          fp32 + pair
    gat_attn<4, 256, 0><<<dim3(4, BIMG), 256, smem12>>>(dh, a1s, a1d, b1, nullptr, dg1, g1_h, g1_l);
    // 12) h2 = g1 @ W2                   [4608, 1024]
    hgemm<<<dim3(1024 / BN, NNODES / BM), GEMM_THREADS, GEMM_SMEM>>>(
        1024, 1024, 1024 / BK, g1_h, g1_l, w2_h, w2_l,
        dh, nullptr, nullptr, nullptr, nullptr, nullptr, 0);
    // 13) prep W3
    prep_w<<<dim3(2560 / 32, 1024 / 32), dim3(32, 8)>>>(1024, 2560, 1024, W3, w3_h, w3_l);
    // 14) g2 = relu(attn2 + b2) + g1     pair only
    gat_attn<4, 256, 1><<<dim3(4, BIMG), 256, smem12>>>(dh, a2s, a2d, b2, dg1, nullptr, g2_h, g2_l);
    // 15) h3 = g2 @ W3                   [4608, 2560]
    hgemm<<<dim3(2560 / BN, NNODES / BM), GEMM_THREADS, GEMM_SMEM>>>(
        2560, 1024, 1024 / BK, g2_h, g2_l, w3_h, w3_l,
        dh, nullptr, nullptr, nullptr, nullptr, nullptr, 0);
    // 16) per-head aggregation -> scratch [4608, 5, 512]
    gat_attn<5, 512, 2><<<dim3(5, BIMG), 256, smem3>>>(dh, a3s, a3d, nullptr, nullptr, da3, nullptr, nullptr);
    // 17) mean over heads + b3 -> output  [4608, 512]
    mean_bias_kernel<<<(NNODES * 512 + 255) / 256, 256>>>(da3, b3, out);
}

// round 16
// speedup vs baseline: 1.5543x; 1.0091x over previous
#include <cuda_runtime.h>
#include <cuda_bf16.h>
#include <cstdint>

// Problem constants
#define BIMG   128
#define NOBJ_  36
#define NNODES (BIMG * NOBJ_)   // 4608
#define QD_    2400
#define VD_    2048
#define KPAD_Q 2432             // 2400 padded to multiple of 32

typedef __nv_bfloat16 bf16;

// ---------------- scratch (device globals; no allocation allowed) -------------
__device__ float g_q  [BIMG   * 2048];          // q fp32 (split-K accumulated)
__device__ float g_h  [NNODES * 2560];          // h1/h2/h3 (fp32, attention input)
__device__ float g_a3 [NNODES * 2560];          // layer-3 per-head agg

__device__ bf16 g_qe_h [BIMG * KPAD_Q],  g_qe_l [BIMG * KPAD_Q];
__device__ bf16 g_obj_h[NNODES * 2048],  g_obj_l[NNODES * 2048];
__device__ bf16 g_x_h  [NNODES * 2048],  g_x_l  [NNODES * 2048];
__device__ bf16 g_g1_h [NNODES * 1024],  g_g1_l [NNODES * 1024];
__device__ bf16 g_g2_h [NNODES * 1024],  g_g2_l [NNODES * 1024];

// weights transposed to [N, Kpad], split into bf16 hi/lo
__device__ bf16 g_Wq_hi[2048 * KPAD_Q], g_Wq_lo[2048 * KPAD_Q];
__device__ bf16 g_Wv_hi[2048 * 2048],   g_Wv_lo[2048 * 2048];
__device__ bf16 g_W1_hi[1024 * 2048],   g_W1_lo[1024 * 2048];
__device__ bf16 g_W2_hi[1024 * 1024],   g_W2_lo[1024 * 1024];
__device__ bf16 g_W3_hi[2560 * 1024],   g_W3_lo[2560 * 1024];

// ---------------- small helpers -------------------------------------------------
__device__ __forceinline__ uint32_t smem_u32(const void* p) {
    uint32_t a;
    asm("{ .reg .u64 t; cvta.to.shared.u64 t, %1; cvt.u32.u64 %0, t; }" : "=r"(a) : "l"(p));
    return a;
}
__device__ __forceinline__ void cp_async16(uint32_t dst, const void* src) {
    asm volatile("cp.async.cg.shared.global [%0], [%1], 16;" :: "r"(dst), "l"(src));
}
__device__ __forceinline__ void cp_commit() { asm volatile("cp.async.commit_group;"); }
__device__ __forceinline__ void ldm_x4(uint32_t* r, uint32_t addr) {
    asm volatile("ldmatrix.sync.aligned.m8n8.x4.shared.b16 {%0,%1,%2,%3}, [%4];"
                 : "=r"(r[0]), "=r"(r[1]), "=r"(r[2]), "=r"(r[3]) : "r"(addr));
}
__device__ __forceinline__ void mma16816(float* c, const uint32_t* a, uint32_t b0, uint32_t b1) {
    asm volatile("mma.sync.aligned.m16n8k16.row.col.f32.bf16.bf16.f32 "
                 "{%0,%1,%2,%3}, {%4,%5,%6,%7}, {%8,%9}, {%0,%1,%2,%3};"
                 : "+f"(c[0]), "+f"(c[1]), "+f"(c[2]), "+f"(c[3])
                 : "r"(a[0]), "r"(a[1]), "r"(a[2]), "r"(a[3]), "r"(b0), "r"(b1));
}
__device__ __forceinline__ void split_bf16(float v, bf16& h, bf16& l) {
    h = __float2bfloat16(v);
    l = __float2bfloat16(v - __bfloat162float(h));
}

// ---------------- weight prep: W[K,N] fp32 -> Wt_hi/lo [N,Kpad] bf16 ------------
__global__ __launch_bounds__(256) void prep_w(
    int K, int N, int Kpad, const float* __restrict__ W,
    bf16* __restrict__ hi, bf16* __restrict__ lo)
{
    __shared__ float t[32][33];
    const int n0 = blockIdx.x * 32, k0 = blockIdx.y * 32;
    const int tx = threadIdx.x, ty = threadIdx.y;   // 32 x 8
#pragma unroll
    for (int i = 0; i < 4; i++) {
        const int k = k0 + ty + i * 8;
        t[ty + i * 8][tx] = (k < K) ? W[(size_t)k * N + n0 + tx] : 0.f;
    }
    __syncthreads();
#pragma unroll
    for (int i = 0; i < 4; i++) {
        const int n = n0 + ty + i * 8;
        const float v = t[tx][ty + i * 8];
        bf16 h, l; split_bf16(v, h, l);
        hi[(size_t)n * Kpad + k0 + tx] = h;
        lo[(size_t)n * Kpad + k0 + tx] = l;
    }
}

// ---------------- activation conv: fp32 [M,K] -> bf16 hi/lo [M,Kpad] ------------
__global__ __launch_bounds__(256) void conv_pair(
    const float* __restrict__ src, bf16* __restrict__ hi, bf16* __restrict__ lo,
    int K, int Kpad)
{
    const int c4 = blockIdx.x * blockDim.x + threadIdx.x;
    if (c4 * 4 >= Kpad) return;
    const int r = blockIdx.y;
    float4 v;
    if (c4 * 4 + 4 <= K) v = *(const float4*)&src[(size_t)r * K + c4 * 4];
    else                 v = make_float4(0.f, 0.f, 0.f, 0.f);
    bf16 h0, l0, h1, l1, h2, l2, h3, l3;
    split_bf16(v.x, h0, l0); split_bf16(v.y, h1, l1);
    split_bf16(v.z, h2, l2); split_bf16(v.w, h3, l3);
    const size_t o = (size_t)r * Kpad + c4 * 4;
    *(__nv_bfloat162*)&hi[o]     = __nv_bfloat162(h0, h1);
    *(__nv_bfloat162*)&hi[o + 2] = __nv_bfloat162(h2, h3);
    *(__nv_bfloat162*)&lo[o]     = __nv_bfloat162(l0, l1);
    *(__nv_bfloat162*)&lo[o + 2] = __nv_bfloat162(l2, l3);
}

// ---------------- zero-fill -----------------------------------------------------
__global__ __launch_bounds__(256) void zero_kernel(float* __restrict__ p, int n)
{
    const int i = blockIdx.x * blockDim.x + threadIdx.x;
    if (i < n) p[i] = 0.f;
}

// ---------------- HMMA bf16x3 GEMM (R9 shape: 256 thr, 2x4 warps, 64x32) --------
// C[M,N] = A[M,K] @ Bt[N,K]^T where A,Bt are hi/lo bf16 splits.
// mode 0: C = acc (fp32)
// mode 2: (acc + bias) * (qmat[row/36] + qbias)  -> Chi/Clo bf16 pair
// mode 3: atomicAdd into C (split-K accumulation; grid.z = #chunks, nk iters each)
#define BM 128
#define BN 128
#define BK 32
#define GEMM_THREADS 256
#define KSTRIDE 40                     // padded smem row stride (bf16 elems)
#define MAT_BYTES (BM * KSTRIDE * 2)   // 10240
#define STAGE_BYTES (4 * MAT_BYTES)    // Ah, Al, Bh, Bl
#define GEMM_SMEM (2 * STAGE_BYTES)    // 81920

__global__ __launch_bounds__(GEMM_THREADS, 2) void hgemm(
    int N, int K, int nk,
    const bf16* __restrict__ Ah, const bf16* __restrict__ Al,
    const bf16* __restrict__ Bh, const bf16* __restrict__ Bl,
    float* __restrict__ C, bf16* __restrict__ Chi, bf16* __restrict__ Clo,
    const float* __restrict__ bias, const float* __restrict__ qmat,
    const float* __restrict__ qbias, int mode)
{
    extern __shared__ __align__(128) char smem[];
    const uint32_t sbase = smem_u32(smem);
    const int tid = threadIdx.x, wid = tid >> 5, lane = tid & 31;
    const int warp_m = wid >> 2, warp_n = wid & 3;       // 2 x 4 warps
    const int brow = blockIdx.y * BM, bcol = blockIdx.x * BN;
    const int k_begin = blockIdx.z * nk * BK;

    float acc[4][4][4];
#pragma unroll
    for (int m = 0; m < 4; m++)
#pragma unroll
        for (int n = 0; n < 4; n++)
#pragma unroll
            for (int e = 0; e < 4; e++) acc[m][n][e] = 0.f;

    // ---- gmem -> smem stage loader (cp.async, 16B granules) ----
    auto load_stage = [&](int buf, int k0) {
        const uint32_t s = sbase + buf * STAGE_BYTES;
#pragma unroll
        for (int it = 0; it < 2; it++) {
            const int idx = tid + it * 256;       // 0..511
            const int r = idx >> 2, c = (idx & 3) * 8;
            const uint32_t so = (uint32_t)(r * KSTRIDE + c) * 2;
            const size_t ga = (size_t)(brow + r) * K + k0 + c;
            const size_t gb = (size_t)(bcol + r) * K + k0 + c;
            cp_async16(s + so,                 Ah + ga);
            cp_async16(s + MAT_BYTES + so,     Al + ga);
            cp_async16(s + 2 * MAT_BYTES + so, Bh + gb);
            cp_async16(s + 3 * MAT_BYTES + so, Bl + gb);
        }
        cp_commit();
    };

    load_stage(0, k_begin);
    if (nk > 1) load_stage(1, k_begin + BK);
    else        cp_commit();

    // ldmatrix lane addressing (byte offsets within a matrix)
    const int a_row = lane & 15, a_k8 = (lane >> 4) * 8;
    const uint32_t aoff = (uint32_t)((warp_m * 64 + a_row) * KSTRIDE + a_k8) * 2;
    const int bmat = lane >> 3, brl = lane & 7;
    const int b_n = warp_n * 32 + (bmat >> 1) * 8 + brl;
    const int b_k = (bmat & 1) * 8;
    const uint32_t boff = (uint32_t)(b_n * KSTRIDE + b_k) * 2;

    for (int kt = 0; kt < nk; kt++) {
        asm volatile("cp.async.wait_group 1;");
        __syncthreads();

        const uint32_t s = sbase + (kt & 1) * STAGE_BYTES;
        const uint32_t sAh = s + aoff;
        const uint32_t sAl = sAh + MAT_BYTES;
        const uint32_t sBh = s + 2 * MAT_BYTES + boff;
        const uint32_t sBl = sBh + MAT_BYTES;

#pragma unroll
        for (int ks = 0; ks < 2; ks++) {
            uint32_t ah[4][4], al[4][4];
#pragma unroll
            for (int m = 0; m < 4; m++) {
                const uint32_t o = (uint32_t)(m * 16 * KSTRIDE + ks * 16) * 2;
                ldm_x4(ah[m], sAh + o);
                ldm_x4(al[m], sAl + o);
            }
#pragma unroll
            for (int np = 0; np < 2; np++) {
                uint32_t bh[4], bl[4];
                const uint32_t o = (uint32_t)(np * 16 * KSTRIDE + ks * 16) * 2;
                ldm_x4(bh, sBh + o);
                ldm_x4(bl, sBl + o);
#pragma unroll
                for (int m = 0; m < 4; m++)
#pragma unroll
                    for (int nsel = 0; nsel < 2; nsel++) {
                        float* a4 = acc[m][np * 2 + nsel];
                        mma16816(a4, ah[m], bh[nsel * 2], bh[nsel * 2 + 1]);
                        mma16816(a4, al[m], bh[nsel * 2], bh[nsel * 2 + 1]);
                        mma16816(a4, ah[m], bl[nsel * 2], bl[nsel * 2 + 1]);
                    }
            }
        }
        __syncthreads();

        const int kn = kt + 2;
        if (kn < nk) load_stage(kn & 1, k_begin + kn * BK);
        else         cp_commit();   // keep group accounting aligned
    }
    asm volatile("cp.async.wait_group 0;");

    // ---- epilogue (register -> gmem direct) ----
#pragma unroll
    for (int m = 0; m < 4; m++) {
        const int r0 = brow + warp_m * 64 + m * 16 + (lane >> 2);
#pragma unroll
        for (int n = 0; n < 4; n++) {
            const int col = bcol + warp_n * 32 + n * 8 + (lane & 3) * 2;
#pragma unroll
            for (int half = 0; half < 2; half++) {
                const int row = r0 + half * 8;
                float v0 = acc[m][n][half * 2 + 0];
                float v1 = acc[m][n][half * 2 + 1];
                if (mode == 2) {
                    const size_t qo = (size_t)(row / NOBJ_) * N + col;
                    v0 = (v0 + bias[col])     * (qmat[qo]     + qbias[col]);
                    v1 = (v1 + bias[col + 1]) * (qmat[qo + 1] + qbias[col + 1]);
                    bf16 h0, l0, h1, l1;
                    split_bf16(v0, h0, l0); split_bf16(v1, h1, l1);
                    *(__nv_bfloat162*)&Chi[(size_t)row * N + col] = __nv_bfloat162(h0, h1);
                    *(__nv_bfloat162*)&Clo[(size_t)row * N + col] = __nv_bfloat162(l0, l1);
                } else if (mode == 3) {
                    atomicAdd(&C[(size_t)row * N + col],     v0);
                    atomicAdd(&C[(size_t)row * N + col + 1], v1);
                } else {
                    *(float2*)&C[(size_t)row * N + col] = make_float2(v0, v1);
                }
            }
        }
    }
}

// ---------------- per-(image, head) dense GAT attention -------------------------
// MODE 0: g = relu(agg+bias); out hi/lo pair only
// MODE 1: g = relu(agg+bias) + res (res reconstructed from resH+resL); pair only
// MODE 2: out = agg (fp32 only)
#define RAWP 37
template <int HEADS, int C, int MODE>
__global__ __launch_bounds__(256) void gat_attn(
    const float* __restrict__ h,
    const float* __restrict__ a_src, const float* __restrict__ a_dst,
    const float* __restrict__ bias,
    const bf16* __restrict__ resH, const bf16* __restrict__ resL,
    float* __restrict__ out, bf16* __restrict__ outH, bf16* __restrict__ outL)
{
    extern __shared__ float sm[];
    float* hs  = sm;                       // 36*C
    float* raw = hs + NOBJ_ * C;           // 36*RAWP  ([j][i])
    float* als = raw + NOBJ_ * RAWP;       // 36
    float* ald = als + NOBJ_;              // 36
    float* mj  = ald + NOBJ_;              // 36
    float* inv = mj + NOBJ_;               // 36

    const int head = blockIdx.x;
    const int b    = blockIdx.y;
    const int tid  = threadIdx.x;
    const int rowstride = HEADS * C;

    // load the 36 x C head-slice into smem (vectorized)
#pragma unroll
    for (int idx = tid * 4; idx < NOBJ_ * C; idx += 256 * 4) {
        const int i = idx / C, c = idx % C;
        *(float4*)&hs[idx] =
            *(const float4*)&h[(size_t)(b * NOBJ_ + i) * rowstride + head * C + c];
    }
    __syncthreads();

    // per-node attention logits: warp-per-row dot products
    const int warp = tid >> 5, lane = tid & 31;
    for (int i = warp; i < NOBJ_; i += 8) {
        float s = 0.f, d = 0.f;
#pragma unroll
        for (int c = lane; c < C; c += 32) {
            const float hv = hs[i * C + c];
            s += hv * a_src[head * C + c];
            d += hv * a_dst[head * C + c];
        }
#pragma unroll
        for (int o = 16; o > 0; o >>= 1) {
            s += __shfl_down_sync(0xFFFFFFFFu, s, o);
            d += __shfl_down_sync(0xFFFFFFFFu, d, o);
        }
        if (lane == 0) { als[i] = s; ald[i] = d; }
    }
    __syncthreads();

    // raw logits, [j][i] layout (parallel over all 1296 pairs)
    for (int idx = tid; idx < NOBJ_ * NOBJ_; idx += 256) {
        const int j = idx / NOBJ_, i = idx - j * NOBJ_;
        float x = als[i] + ald[j];
        raw[j * RAWP + i] = x > 0.f ? x : 0.2f * x;
    }
    __syncthreads();

    // per-destination max
    if (tid < NOBJ_) {
        float m = -1e30f;
#pragma unroll
        for (int i = 0; i < NOBJ_; i++) m = fmaxf(m, raw[tid * RAWP + i]);
        mj[tid] = m;
    }
    __syncthreads();

    // exp (parallel)
    for (int idx = tid; idx < NOBJ_ * NOBJ_; idx += 256) {
        const int j = idx / NOBJ_, i = idx - j * NOBJ_;
        raw[j * RAWP + i] = __expf(raw[j * RAWP + i] - mj[j]);
    }
    __syncthreads();

    // per-destination sum -> inverse
    if (tid < NOBJ_) {
        float s = 0.f;
#pragma unroll
        for (int i = 0; i < NOBJ_; i++) s += raw[tid * RAWP + i];
        inv[tid] = 1.0f / (s + 1e-16f);
    }
    __syncthreads();

    // aggregation: out[j, c4] = inv[j] * sum_i raw[j][i] * hs[i][c4]  (float4)
    const int QC = C / 4;
    for (int qidx = tid; qidx < NOBJ_ * QC; qidx += 256) {
        const int j = qidx / QC, c4 = qidx - j * QC;
        const float* rj = raw + j * RAWP;
        float4 acc = make_float4(0.f, 0.f, 0.f, 0.f);
#pragma unroll
        for (int i = 0; i < NOBJ_; i++) {
            const float a = rj[i];
            const float4 hv = *(const float4*)&hs[i * C + c4 * 4];
            acc.x += a * hv.x; acc.y += a * hv.y;
            acc.z += a * hv.z; acc.w += a * hv.w;
        }
        const float vj = inv[j];
        acc.x *= vj; acc.y *= vj; acc.z *= vj; acc.w *= vj;

        const int c = c4 * 4;
        const size_t o = (size_t)(b * NOBJ_ + j) * rowstride + head * C + c;
        if (MODE == 2) {
            *(float4*)&out[o] = acc;
        } else {
            const float4 bv = *(const float4*)&bias[head * C + c];
            float4 v = make_float4(acc.x + bv.x, acc.y + bv.y, acc.z + bv.z, acc.w + bv.w);
            v.x = v.x > 0.f ? v.x : 0.f;  v.y = v.y > 0.f ? v.y : 0.f;
            v.z = v.z > 0.f ? v.z : 0.f;  v.w = v.w > 0.f ? v.w : 0.f;
            if (MODE == 1) {
                // residual reconstructed from hi/lo pair (error ~2^-17, negligible)
                const __nv_bfloat162 rh0 = *(const __nv_bfloat162*)&resH[o];
                const __nv_bfloat162 rh1 = *(const __nv_bfloat162*)&resH[o + 2];
                const __nv_bfloat162 rl0 = *(const __nv_bfloat162*)&resL[o];
                const __nv_bfloat162 rl1 = *(const __nv_bfloat162*)&resL[o + 2];
                v.x += __bfloat162float(rh0.x) + __bfloat162float(rl0.x);
                v.y += __bfloat162float(rh0.y) + __bfloat162float(rl0.y);
                v.z += __bfloat162float(rh1.x) + __bfloat162float(rl1.x);
                v.w += __bfloat162float(rh1.y) + __bfloat162float(rl1.y);
            }
            bf16 h0, l0, h1, l1, h2, l2, h3, l3;
            split_bf16(v.x, h0, l0); split_bf16(v.y, h1, l1);
            split_bf16(v.z, h2, l2); split_bf16(v.w, h3, l3);
            *(__nv_bfloat162*)&outH[o]     = __nv_bfloat162(h0, h1);
            *(__nv_bfloat162*)&outH[o + 2] = __nv_bfloat162(h2, h3);
            *(__nv_bfloat162*)&outL[o]     = __nv_bfloat162(l0, l1);
            *(__nv_bfloat162*)&outL[o + 2] = __nv_bfloat162(l2, l3);
        }
    }
}

// ---------------- layer-3 mean over heads + bias --------------------------------
__global__ __launch_bounds__(256) void mean_bias_kernel(
    const float* __restrict__ scr, const float* __restrict__ b3, float* __restrict__ out)
{
    const int idx = blockIdx.x * blockDim.x + threadIdx.x;
    if (idx >= NNODES * 512) return;
    const int n = idx / 512, c = idx % 512;
    float s = 0.f;
#pragma unroll
    for (int hd = 0; hd < 5; hd++) s += scr[(size_t)n * 2560 + hd * 512 + c];
    out[idx] = s * 0.2f + b3[c];
}

// ------------------------------- launch ------------------------------------------
template <typename T>
static T* sym_addr(const void* symbol)
{
    void* p = nullptr;
    cudaGetSymbolAddress(&p, symbol);
    return (T*)p;
}

extern "C" void kernel_launch(void* const* d_in, const int* in_sizes, int n_in,
                              void* d_out, int out_size)
{
    (void)in_sizes; (void)n_in; (void)out_size;
    const float* qe   = (const float*)d_in[0];
    const float* obj  = (const float*)d_in[1];
    // d_in[2] = edge_index (ignored: graph fully-connected per image)
    const float* Wq   = (const float*)d_in[3];
    const float* bq   = (const float*)d_in[4];
    const float* Wv   = (const float*)d_in[5];
    const float* bv   = (const float*)d_in[6];
    const float* W1   = (const float*)d_in[7];
    const float* a1s  = (const float*)d_in[8];
    const float* a1d  = (const float*)d_in[9];
    const float* b1   = (const float*)d_in[10];
    const float* W2   = (const float*)d_in[11];
    const float* a2s  = (const float*)d_in[12];
    const float* a2d  = (const float*)d_in[13];
    const float* b2   = (const float*)d_in[14];
    const float* W3   = (const float*)d_in[15];
    const float* a3s  = (const float*)d_in[16];
    const float* a3d  = (const float*)d_in[17];
    const float* b3   = (const float*)d_in[18];
    float* out = (float*)d_out;

    float* dq   = sym_addr<float>(g_q);
    float* dh   = sym_addr<float>(g_h);
    float* da3  = sym_addr<float>(g_a3);
    bf16* qe_h  = sym_addr<bf16>(g_qe_h);   bf16* qe_l  = sym_addr<bf16>(g_qe_l);
    bf16* obj_h = sym_addr<bf16>(g_obj_h);  bf16* obj_l = sym_addr<bf16>(g_obj_l);
    bf16* x_h   = sym_addr<bf16>(g_x_h);    bf16* x_l   = sym_addr<bf16>(g_x_l);
    bf16* g1_h  = sym_addr<bf16>(g_g1_h);   bf16* g1_l  = sym_addr<bf16>(g_g1_l);
    bf16* g2_h  = sym_addr<bf16>(g_g2_h);   bf16* g2_l  = sym_addr<bf16>(g_g2_l);
    bf16* wq_h  = sym_addr<bf16>(g_Wq_hi);  bf16* wq_l  = sym_addr<bf16>(g_Wq_lo);
    bf16* wv_h  = sym_addr<bf16>(g_Wv_hi);  bf16* wv_l  = sym_addr<bf16>(g_Wv_lo);
    bf16* w1_h  = sym_addr<bf16>(g_W1_hi);  bf16* w1_l  = sym_addr<bf16>(g_W1_lo);
    bf16* w2_h  = sym_addr<bf16>(g_W2_hi);  bf16* w2_l  = sym_addr<bf16>(g_W2_lo);
    bf16* w3_h  = sym_addr<bf16>(g_W3_hi);  bf16* w3_l  = sym_addr<bf16>(g_W3_lo);

    cudaFuncSetAttribute(hgemm, cudaFuncAttributeMaxDynamicSharedMemorySize, GEMM_SMEM);
    const int smem12 = (NOBJ_ * 256 + NOBJ_ * RAWP + 4 * NOBJ_) * sizeof(float);
    const int smem3  = (NOBJ_ * 512 + NOBJ_ * RAWP + 4 * NOBJ_) * sizeof(float);
    cudaFuncSetAttribute(gat_attn<5, 512, 2>, cudaFuncAttributeMaxDynamicSharedMemorySize, smem3);

    // single stream, R9 order, split-K x19 q-GEMM
    // 1) conv qe
    conv_pair<<<dim3((KPAD_Q / 4 + 255) / 256, BIMG), 256>>>(qe, qe_h, qe_l, QD_, KPAD_Q);
    // 2) prep Wq
    prep_w<<<dim3(2048 / 32, KPAD_Q / 32), dim3(32, 8)>>>(QD_, 2048, KPAD_Q, Wq, wq_h, wq_l);
    // 3) zero q accumulator
    zero_kernel<<<(BIMG * 2048 + 255) / 256, 256>>>(dq, BIMG * 2048);
    // 4) q_raw = qe @ Wq (split-K x19, atomicAdd)   [128, 2048]
    hgemm<<<dim3(2048 / BN, 1, 19), GEMM_THREADS, GEMM_SMEM>>>(
        2048, KPAD_Q, (KPAD_Q / BK) / 19, qe_h, qe_l, wq_h, wq_l,
        dq, nullptr, nullptr, nullptr, nullptr, nullptr, 3);
    // 5) conv obj
    conv_pair<<<dim3((2048 / 4 + 255) / 256, NNODES), 256>>>(obj, obj_h, obj_l, VD_, 2048);
    // 6) prep Wv
    prep_w<<<dim3(2048 / 32, 2048 / 32), dim3(32, 8)>>>(2048, 2048, 2048, Wv, wv_h, wv_l);
    // 7) x = (obj @ Wv + bv) * (q_raw + bq) -> bf16 pair  [4608, 2048]
    hgemm<<<dim3(2048 / BN, NNODES / BM), GEMM_THREADS, GEMM_SMEM>>>(
        2048, 2048, 2048 / BK, obj_h, obj_l, wv_h, wv_l,
        nullptr, x_h, x_l, bv, dq, bq, 2);
    // 8) prep W1
    prep_w<<<dim3(1024 / 32, 2048 / 32), dim3(32, 8)>>>(2048, 1024, 2048, W1, w1_h, w1_l);
    // 9) h1 = x @ W1                     [4608, 1024]
    hgemm<<<dim3(1024 / BN, NNODES / BM), GEMM_THREADS, GEMM_SMEM>>>(
        1024, 2048, 2048 / BK, x_h, x_l, w1_h, w1_l,
        dh, nullptr, nullptr, nullptr, nullptr, nullptr, 0);
    // 10) prep W2
    prep_w<<<dim3(1024 / 32, 1024 / 32), dim3(32, 8)>>>(1024, 1024, 1024, W2, w2_h, w2_l);
    // 11) g1 = relu(attn1 + b1)          bf16 pair only
    gat_attn<4, 256, 0><<<dim3(4, BIMG), 256, smem12>>>(
        dh, a1s, a1d, b1, nullptr, nullptr, nullptr, g1_h, g1_l);
    // 12) h2 = g1 @ W2                   [4608, 1024]
    hgemm<<<dim3(1024 / BN, NNODES / BM), GEMM_THREADS, GEMM_SMEM>>>(
        1024, 1024, 1024 / BK, g1_h, g1_l, w2_h, w2_l,
        dh, nullptr, nullptr, nullptr, nullptr, nullptr, 0);
    // 13) prep W3
    prep_w<<<dim3(2560 / 32, 1024 / 32), dim3(32, 8)>>>(1024, 2560, 1024, W3, w3_h, w3_l);
    // 14) g2 = relu(attn2 + b2) + g1     (g1 reconstructed from pair)
    gat_attn<4, 256, 1><<<dim3(4, BIMG), 256, smem12>>>(
        dh, a2s, a2d, b2, g1_h, g1_l, nullptr, g2_h, g2_l);
    // 15) h3 = g2 @ W3                   [4608, 2560]
    hgemm<<<dim3(2560 / BN, NNODES / BM), GEMM_THREADS, GEMM_SMEM>>>(
        2560, 1024, 1024 / BK, g2_h, g2_l, w3_h, w3_l,
        dh, nullptr, nullptr, nullptr, nullptr, nullptr, 0);
    // 16) per-head aggregation -> scratch [4608, 5, 512]
    gat_attn<5, 512, 2><<<dim3(5, BIMG), 256, smem3>>>(
        dh, a3s, a3d, nullptr, nullptr, nullptr, da3, nullptr, nullptr);
    // 17) mean over heads + b3 -> output  [4608, 512]
    mean_bias_kernel<<<(NNODES * 512 + 255) / 256, 256>>>(da3, b3, out);
}